// round 11
// baseline (speedup 1.0000x reference)
#include <cuda_runtime.h>
#include <cuda_fp16.h>
#include <cstdint>

#define NMAX 50000
#define EMAX 800000
#define GNUM 512
#define HID 64
#define LAY 5
#define HL 320
#define BN_EPS 1e-5f
#define PB 444
#define NT 512
#define NSLICE 16
#define STATSZ (LAY * 256)

// ---------------- static scratch ----------------
__device__ __half g_z16[(size_t)NMAX * HID];    // post-GEMM1 pre-BN z, fp16
__device__ __half g_h16[(size_t)NMAX * HL];     // RAW gemm2 outputs (pre-BN), fp16
__device__ float  g_statp[NSLICE * STATSZ];
__device__ int    g_deg[NMAX];
__device__ int    g_rowptr[NMAX + 1];
__device__ int    g_cur[NMAX];
__device__ int    g_part[256];
__device__ int    g_partscan[256];
__device__ int    g_csrc[EMAX];
__device__ int    g_is64_e, g_is64_b;
__device__ unsigned g_count = 0, g_epoch = 0;

__device__ __forceinline__ long ldidx(const void* p, long i, int is64) {
    return is64 ? (long)((const long long*)p)[i] : (long)((const int*)p)[i];
}

__device__ __forceinline__ unsigned ld_epoch() {
    unsigned v;
    asm volatile("ld.global.cg.u32 %0, [%1];" : "=r"(v) : "l"(&g_epoch) : "memory");
    return v;
}

__device__ __forceinline__ void gbar() {
    __syncthreads();
    if (threadIdx.x == 0) {
        __threadfence();
        unsigned e = ld_epoch();
        if (atomicAdd(&g_count, 1) == gridDim.x - 1) {
            atomicExch(&g_count, 0u);
            __threadfence();
            atomicExch(&g_epoch, e + 1);
        } else {
            unsigned cur;
            do { __nanosleep(20); cur = ld_epoch(); } while (cur == e);
        }
        __threadfence();
    }
    __syncthreads();
}

// ---------------- shared memory ----------------
struct SmGemm {
    float w[64][64];
    float in[64][65];
    float a[64];
    float b[64];
    float bias[64];
    float st[128];
};
struct SmPool { float a[HL]; float b[HL]; };
struct SmScan { int sh[NT + 1]; };
struct SmL0   { float xr[64]; float st[128]; };
union __align__(16) SmU {
    SmGemm g; SmPool p; SmScan s; SmL0 l0;
};

__global__ void __launch_bounds__(NT, 3) fused_all(
    const float* __restrict__ x, const void* __restrict__ ei,
    const void* __restrict__ batch,
    const float* __restrict__ w1_0, const float* __restrict__ w1_rest,
    const float* __restrict__ b1,
    const float* __restrict__ gm, const float* __restrict__ bm,
    const float* __restrict__ w2, const float* __restrict__ b2,
    const float* __restrict__ go, const float* __restrict__ bo,
    const float* __restrict__ lin_w, const float* __restrict__ lin_b,
    float* __restrict__ out, int n, int E, int bcount, float invN)
{
    __shared__ SmU sm;
    int t = threadIdx.x, b = blockIdx.x, nb = gridDim.x;
    int lane = t & 31, warp = t >> 5;
    long gstride = (long)nb * NT;
    int slice = (b & (NSLICE - 1)) * STATSZ;

    // ---------- P0: zero + detect ----------
    for (long i = (long)b * NT + t; i < n; i += gstride) g_deg[i] = 0;
    for (long i = (long)b * NT + t; i < NSLICE * STATSZ; i += gstride) g_statp[i] = 0.f;
    if (b == 1) {
        const int* p = (const int*)ei;
        int f = 0;
        for (int i = t; i < 4096; i += NT) if (p[2 * i + 1] != 0) f = 1;
        f = __syncthreads_or(f);
        if (t == 0) g_is64_e = (f == 0);
        const int* q = (const int*)batch;
        int hf = bcount / 2;
        int f2 = 0;
        for (int i = t; i < 2048; i += NT) {
            int pos = hf - 1 - i;
            if (pos >= 0 && q[2 * pos + 1] != 0) f2 = 1;
        }
        f2 = __syncthreads_or(f2);
        if (t == 0) g_is64_b = (f2 == 0);
    }
    gbar();

    // ---------- P1: degree histogram ----------
    {
        int is64 = g_is64_e;
        for (long e0 = (long)b * NT + t; e0 < E; e0 += gstride) {
            int dst = (int)ldidx(ei, (long)E + e0, is64);
            atomicAdd(&g_deg[dst], 1);
        }
    }
    gbar();

    int nch = (n + NT - 1) / NT;

    // ---------- P2: chunk sums ----------
    for (int c = b; c < nch; c += nb) {
        int i = c * NT + t;
        sm.s.sh[t] = (i < n) ? g_deg[i] : 0;
        __syncthreads();
        for (int off = NT / 2; off > 0; off >>= 1) {
            if (t < off) sm.s.sh[t] += sm.s.sh[t + off];
            __syncthreads();
        }
        if (t == 0) g_part[c] = sm.s.sh[0];
        __syncthreads();
    }
    gbar();

    // ---------- P3: scan of chunk sums ----------
    if (b == 0) {
        int v = (t < nch) ? g_part[t] : 0;
        sm.s.sh[t] = v;
        __syncthreads();
        for (int off = 1; off < NT; off <<= 1) {
            int xv = (t >= off) ? sm.s.sh[t - off] : 0;
            __syncthreads();
            sm.s.sh[t] += xv;
            __syncthreads();
        }
        if (t < nch) g_partscan[t] = sm.s.sh[t] - v;
    }
    gbar();

    // ---------- P4: rowptr ----------
    for (int c = b; c < nch; c += nb) {
        int i = c * NT + t;
        int v = (i < n) ? g_deg[i] : 0;
        sm.s.sh[t] = v;
        __syncthreads();
        for (int off = 1; off < NT; off <<= 1) {
            int xv = (t >= off) ? sm.s.sh[t - off] : 0;
            __syncthreads();
            sm.s.sh[t] += xv;
            __syncthreads();
        }
        if (i < n) {
            int rp = g_partscan[c] + sm.s.sh[t] - v;
            g_rowptr[i] = rp;
            g_cur[i] = rp;
            if (i == n - 1) g_rowptr[n] = E;
        }
        __syncthreads();
    }
    gbar();

    // ---------- P5: fill CSR ----------
    {
        int is64 = g_is64_e;
        for (long e0 = (long)b * NT + t; e0 < E; e0 += gstride) {
            int src = (int)ldidx(ei, e0, is64);
            int dst = (int)ldidx(ei, (long)E + e0, is64);
            int pos = atomicAdd(&g_cur[dst], 1);
            g_csrc[pos] = src;
        }
    }
    gbar();

    int ntiles = (n + 63) / 64;

    // ---------- P6: layer-0 ----------
    for (int i = t; i < 128; i += NT) sm.l0.st[i] = 0.f;
    __syncthreads();
    for (int tile = b; tile < ntiles; tile += nb) {
        int r0 = tile * 64;
        for (int rr = 0; rr < 4; rr++) {
            int rl = warp * 4 + rr;
            int row = r0 + rl;
            float acc = 0.f;
            if (row < n) {
                int beg = g_rowptr[row], end = g_rowptr[row + 1];
                for (int j = beg + lane; j < end; j += 32)
                    acc += x[g_csrc[j]];
            }
            #pragma unroll
            for (int o = 16; o > 0; o >>= 1)
                acc += __shfl_xor_sync(0xFFFFFFFFu, acc, o);
            if (lane == 0)
                sm.l0.xr[rl] = (row < n) ? (acc + x[row]) : 0.f;
        }
        __syncthreads();
        int c = t & 63, g4 = t >> 6;
        float wc = w1_0[c], bc = b1[c];
        float s = 0.f, q = 0.f;
        #pragma unroll
        for (int i = 0; i < 8; i++) {
            int row = r0 + g4 * 8 + i;
            if (row < n) {
                float zv = sm.l0.xr[g4 * 8 + i] * wc + bc;
                g_z16[(size_t)row * HID + c] = __float2half(zv);
                s += zv; q += zv * zv;
            }
        }
        atomicAdd(&sm.l0.st[c], s);
        atomicAdd(&sm.l0.st[64 + c], q);
        __syncthreads();
    }
    if (t < 128) atomicAdd(&g_statp[slice + t], sm.l0.st[t]);
    gbar();

    // ---------- layers ----------
    for (int l = 0; l < LAY; l++) {
        // ----- gemm1 + quarter-split uint4 gather (l >= 1) -----
        if (l > 0) {
            int pc = (l - 1) * HID;
            int pso = (l - 1) * 256 + 128;
            if (t < 64) {
                float s1 = 0.f, s2 = 0.f;
                #pragma unroll 4
                for (int sl = 0; sl < NSLICE; sl++) {
                    const float* sp = g_statp + sl * STATSZ + pso;
                    s1 += __ldcg(sp + t);
                    s2 += __ldcg(sp + 64 + t);
                }
                float mean = s1 * invN;
                float var  = s2 * invN - mean * mean;
                float a = go[pc + t] * rsqrtf(var + BN_EPS);
                sm.g.a[t] = a;
                sm.g.b[t] = bo[pc + t] - mean * a;
                sm.g.bias[t] = b1[l * HID + t];
            }
            const float* w = w1_rest + (size_t)(l - 1) * 4096;
            for (int idx = t; idx < 4096; idx += NT)
                sm.g.w[idx >> 6][idx & 63] = w[idx];
            for (int i = t; i < 128; i += NT) sm.g.st[i] = 0.f;
            __syncthreads();

            int qtr = lane >> 3;          // edge slot 0..3
            int i8  = lane & 7;           // 8 halfs each: channels i8*8 .. i8*8+7
            float4 ca0 = *(const float4*)&sm.g.a[i8 * 8];
            float4 ca1 = *(const float4*)&sm.g.a[i8 * 8 + 4];
            float4 cb0 = *(const float4*)&sm.g.b[i8 * 8];
            float4 cb1 = *(const float4*)&sm.g.b[i8 * 8 + 4];
            int so = l * 256;

            for (int tile = b; tile < ntiles; tile += nb) {
                int r0 = tile * 64;
                for (int rr = 0; rr < 4; rr++) {
                    int rl = warp * 4 + rr;
                    int row = r0 + rl;
                    float4 A0 = make_float4(0.f, 0.f, 0.f, 0.f);
                    float4 A1 = make_float4(0.f, 0.f, 0.f, 0.f);
                    auto accum = [&](uint4 raw) {
                        float2 f0 = __half22float2(*(__half2*)&raw.x);
                        float2 f1 = __half22float2(*(__half2*)&raw.y);
                        float2 f2 = __half22float2(*(__half2*)&raw.z);
                        float2 f3 = __half22float2(*(__half2*)&raw.w);
                        A0.x += fmaxf(fmaf(f0.x, ca0.x, cb0.x), 0.f);
                        A0.y += fmaxf(fmaf(f0.y, ca0.y, cb0.y), 0.f);
                        A0.z += fmaxf(fmaf(f1.x, ca0.z, cb0.z), 0.f);
                        A0.w += fmaxf(fmaf(f1.y, ca0.w, cb0.w), 0.f);
                        A1.x += fmaxf(fmaf(f2.x, ca1.x, cb1.x), 0.f);
                        A1.y += fmaxf(fmaf(f2.y, ca1.y, cb1.y), 0.f);
                        A1.z += fmaxf(fmaf(f3.x, ca1.z, cb1.z), 0.f);
                        A1.w += fmaxf(fmaf(f3.y, ca1.w, cb1.w), 0.f);
                    };
                    if (row < n) {
                        int beg = g_rowptr[row], end = g_rowptr[row + 1];
                        int j = beg + qtr;
                        while (j + 4 < end) {
                            int s0 = g_csrc[j];
                            int s1 = g_csrc[j + 4];
                            uint4 r0v = *(const uint4*)(g_h16 + (size_t)s0 * HL + pc + i8 * 8);
                            uint4 r1v = *(const uint4*)(g_h16 + (size_t)s1 * HL + pc + i8 * 8);
                            accum(r0v);
                            accum(r1v);
                            j += 8;
                        }
                        if (j < end) {
                            int s0 = g_csrc[j];
                            uint4 r0v = *(const uint4*)(g_h16 + (size_t)s0 * HL + pc + i8 * 8);
                            accum(r0v);
                        }
                    }
                    // combine 4 quarters (same i8 channels)
                    #pragma unroll
                    for (int o = 8; o <= 16; o <<= 1) {
                        A0.x += __shfl_xor_sync(0xFFFFFFFFu, A0.x, o);
                        A0.y += __shfl_xor_sync(0xFFFFFFFFu, A0.y, o);
                        A0.z += __shfl_xor_sync(0xFFFFFFFFu, A0.z, o);
                        A0.w += __shfl_xor_sync(0xFFFFFFFFu, A0.w, o);
                        A1.x += __shfl_xor_sync(0xFFFFFFFFu, A1.x, o);
                        A1.y += __shfl_xor_sync(0xFFFFFFFFu, A1.y, o);
                        A1.z += __shfl_xor_sync(0xFFFFFFFFu, A1.z, o);
                        A1.w += __shfl_xor_sync(0xFFFFFFFFu, A1.w, o);
                    }
                    if (qtr == 0) {
                        if (row < n) {
                            uint4 raw = *(const uint4*)(g_h16 + (size_t)row * HL + pc + i8 * 8);
                            accum(raw);
                        }
                        float* ip = &sm.g.in[rl][i8 * 8];
                        ip[0] = A0.x; ip[1] = A0.y; ip[2] = A0.z; ip[3] = A0.w;
                        ip[4] = A1.x; ip[5] = A1.y; ip[6] = A1.z; ip[7] = A1.w;
                    }
                }
                __syncthreads();
                // GEMM: 512 threads, 8 outputs each; write z as fp16
                int r = t & 63, c0 = (t >> 6) * 8;
                float acc[8];
                #pragma unroll
                for (int j = 0; j < 8; j++) acc[j] = sm.g.bias[c0 + j];
                #pragma unroll
                for (int k = 0; k < 64; k++) {
                    float a = sm.g.in[r][k];
                    float4 wv0 = *(const float4*)&sm.g.w[k][c0];
                    float4 wv1 = *(const float4*)&sm.g.w[k][c0 + 4];
                    acc[0] = fmaf(a, wv0.x, acc[0]);
                    acc[1] = fmaf(a, wv0.y, acc[1]);
                    acc[2] = fmaf(a, wv0.z, acc[2]);
                    acc[3] = fmaf(a, wv0.w, acc[3]);
                    acc[4] = fmaf(a, wv1.x, acc[4]);
                    acc[5] = fmaf(a, wv1.y, acc[5]);
                    acc[6] = fmaf(a, wv1.z, acc[6]);
                    acc[7] = fmaf(a, wv1.w, acc[7]);
                }
                int gr = r0 + r;
                bool valid = gr < n;
                if (valid) {
                    uint4 pk;
                    __half2* ph = (__half2*)&pk;
                    ph[0] = __float22half2_rn(make_float2(acc[0], acc[1]));
                    ph[1] = __float22half2_rn(make_float2(acc[2], acc[3]));
                    ph[2] = __float22half2_rn(make_float2(acc[4], acc[5]));
                    ph[3] = __float22half2_rn(make_float2(acc[6], acc[7]));
                    *(uint4*)(g_z16 + (size_t)gr * HID + c0) = pk;
                }
                #pragma unroll
                for (int j = 0; j < 8; j++) {
                    float s = valid ? acc[j] : 0.f;
                    float q = s * s;
                    #pragma unroll
                    for (int o = 16; o > 0; o >>= 1) {
                        s += __shfl_down_sync(0xFFFFFFFFu, s, o);
                        q += __shfl_down_sync(0xFFFFFFFFu, q, o);
                    }
                    if (lane == 0) {
                        atomicAdd(&sm.g.st[c0 + j], s);
                        atomicAdd(&sm.g.st[64 + c0 + j], q);
                    }
                }
                __syncthreads();
            }
            if (t < 128) atomicAdd(&g_statp[slice + so + t], sm.g.st[t]);
            gbar();
        }

        // ----- gemm2: fp16 z in, fp16 h out -----
        {
            int zso = l * 256;
            if (t < 64) {
                float s1 = 0.f, s2 = 0.f;
                #pragma unroll 4
                for (int sl = 0; sl < NSLICE; sl++) {
                    const float* sp = g_statp + sl * STATSZ + zso;
                    s1 += __ldcg(sp + t);
                    s2 += __ldcg(sp + 64 + t);
                }
                float mean = s1 * invN;
                float var  = s2 * invN - mean * mean;
                float a = gm[l * HID + t] * rsqrtf(var + BN_EPS);
                sm.g.a[t] = a;
                sm.g.b[t] = bm[l * HID + t] - mean * a;
                sm.g.bias[t] = b2[l * HID + t];
            }
            const float* w = w2 + (size_t)l * 4096;
            for (int idx = t; idx < 4096; idx += NT)
                sm.g.w[idx >> 6][idx & 63] = w[idx];
            for (int i = t; i < 128; i += NT) sm.g.st[i] = 0.f;
            __syncthreads();

            int vso = l * 256 + 128;

            for (int tile = b; tile < ntiles; tile += nb) {
                int r0 = tile * 64;
                // load z (fp16), BN+relu, stage to smem: 512 chunks of 8 halfs
                {
                    int idx = t;           // exactly one chunk per thread
                    int r = idx >> 3, k8 = idx & 7;
                    int gr = r0 + r;
                    float v[8];
                    if (gr < n) {
                        uint4 raw = *(const uint4*)(g_z16 + (size_t)gr * HID + k8 * 8);
                        __half2* ph = (__half2*)&raw;
                        #pragma unroll
                        for (int m = 0; m < 4; m++) {
                            float2 f = __half22float2(ph[m]);
                            int c = k8 * 8 + m * 2;
                            v[m*2+0] = fmaxf(fmaf(f.x, sm.g.a[c],     sm.g.b[c]),     0.f);
                            v[m*2+1] = fmaxf(fmaf(f.y, sm.g.a[c + 1], sm.g.b[c + 1]), 0.f);
                        }
                    } else {
                        #pragma unroll
                        for (int m = 0; m < 8; m++) v[m] = 0.f;
                    }
                    float* ip = &sm.g.in[r][k8 * 8];
                    #pragma unroll
                    for (int m = 0; m < 8; m++) ip[m] = v[m];
                }
                __syncthreads();
                int r = t & 63, c0 = (t >> 6) * 8;
                float acc[8];
                #pragma unroll
                for (int j = 0; j < 8; j++) acc[j] = sm.g.bias[c0 + j];
                #pragma unroll
                for (int k = 0; k < 64; k++) {
                    float a = sm.g.in[r][k];
                    float4 wv0 = *(const float4*)&sm.g.w[k][c0];
                    float4 wv1 = *(const float4*)&sm.g.w[k][c0 + 4];
                    acc[0] = fmaf(a, wv0.x, acc[0]);
                    acc[1] = fmaf(a, wv0.y, acc[1]);
                    acc[2] = fmaf(a, wv0.z, acc[2]);
                    acc[3] = fmaf(a, wv0.w, acc[3]);
                    acc[4] = fmaf(a, wv1.x, acc[4]);
                    acc[5] = fmaf(a, wv1.y, acc[5]);
                    acc[6] = fmaf(a, wv1.z, acc[6]);
                    acc[7] = fmaf(a, wv1.w, acc[7]);
                }
                int gr = r0 + r;
                bool valid = gr < n;
                if (valid) {
                    uint4 pk;
                    __half2* ph = (__half2*)&pk;
                    ph[0] = __float22half2_rn(make_float2(acc[0], acc[1]));
                    ph[1] = __float22half2_rn(make_float2(acc[2], acc[3]));
                    ph[2] = __float22half2_rn(make_float2(acc[4], acc[5]));
                    ph[3] = __float22half2_rn(make_float2(acc[6], acc[7]));
                    *(uint4*)(g_h16 + (size_t)gr * HL + l * HID + c0) = pk;
                }
                #pragma unroll
                for (int j = 0; j < 8; j++) {
                    float s = valid ? acc[j] : 0.f;
                    float q = s * s;
                    #pragma unroll
                    for (int o = 16; o > 0; o >>= 1) {
                        s += __shfl_down_sync(0xFFFFFFFFu, s, o);
                        q += __shfl_down_sync(0xFFFFFFFFu, q, o);
                    }
                    if (lane == 0) {
                        atomicAdd(&sm.g.st[c0 + j], s);
                        atomicAdd(&sm.g.st[64 + c0 + j], q);
                    }
                }
                __syncthreads();
            }
            if (t < 128) atomicAdd(&g_statp[slice + vso + t], sm.g.st[t]);
            gbar();
        }
    }

    // ---------- pool + classifier ----------
    for (int c = t; c < HL; c += NT) {
        int l = c >> 6, ch = c & 63;
        int vso = l * 256 + 128;
        float s1 = 0.f, s2 = 0.f;
        for (int sl = 0; sl < NSLICE; sl++) {
            const float* sp = g_statp + sl * STATSZ + vso;
            s1 += __ldcg(sp + ch);
            s2 += __ldcg(sp + 64 + ch);
        }
        float mean = s1 * invN;
        float var  = s2 * invN - mean * mean;
        float a = go[c] * rsqrtf(var + BN_EPS);
        sm.p.a[c] = a;
        sm.p.b[c] = bo[c] - mean * a;
    }
    __syncthreads();
    {
        int is64 = g_is64_b;
        int warpsTotal = nb * 16;
        int gw = b * 16 + warp;
        for (int g = gw; g < GNUM; g += warpsTotal) {
            int se = n;
            if (lane < 2) {
                int key = g + lane;
                int lo = 0, hi = n;
                while (lo < hi) {
                    int mid = (lo + hi) >> 1;
                    if ((int)ldidx(batch, mid, is64) < key) lo = mid + 1;
                    else hi = mid;
                }
                se = lo;
            }
            int s0 = __shfl_sync(0xFFFFFFFFu, se, 0);
            int e0 = __shfl_sync(0xFFFFFFFFu, se, 1);
            float acc0[5], acc1[5];
            #pragma unroll
            for (int k = 0; k < 5; k++) { acc0[k] = 0.f; acc1[k] = 0.f; }
            float xsum = 0.f;
            int cbase = lane * 2;
            for (int r = s0; r < e0; r++) {
                xsum += x[r];
                const __half2* rp = (const __half2*)(g_h16 + (size_t)r * HL);
                #pragma unroll
                for (int k = 0; k < 5; k++) {
                    float2 f = __half22float2(rp[k * 32 + lane]);
                    int c = k * 64 + cbase;
                    acc0[k] += fmaxf(fmaf(f.x, sm.p.a[c], sm.p.b[c]), 0.f);
                    acc1[k] += fmaxf(fmaf(f.y, sm.p.a[c + 1], sm.p.b[c + 1]), 0.f);
                }
            }
            float o0 = 0.f, o1 = 0.f;
            #pragma unroll
            for (int k = 0; k < 5; k++) {
                int c = k * 64 + cbase;
                o0 = fmaf(acc0[k], lin_w[(1 + c) * 2 + 0], o0);
                o1 = fmaf(acc0[k], lin_w[(1 + c) * 2 + 1], o1);
                o0 = fmaf(acc1[k], lin_w[(2 + c) * 2 + 0], o0);
                o1 = fmaf(acc1[k], lin_w[(2 + c) * 2 + 1], o1);
            }
            #pragma unroll
            for (int o = 16; o > 0; o >>= 1) {
                o0 += __shfl_down_sync(0xFFFFFFFFu, o0, o);
                o1 += __shfl_down_sync(0xFFFFFFFFu, o1, o);
            }
            if (lane == 0) {
                out[g * 2 + 0] = o0 + xsum * lin_w[0] + lin_b[0];
                out[g * 2 + 1] = o1 + xsum * lin_w[1] + lin_b[1];
            }
        }
    }
}

// ---------------- launch ----------------
extern "C" void kernel_launch(void* const* d_in, const int* in_sizes, int n_in,
                              void* d_out, int out_size)
{
    const float* x      = (const float*)d_in[0];
    const void*  ei     = d_in[1];
    const void*  batch  = d_in[2];
    const float* w1_0   = (const float*)d_in[3];
    const float* w1_rest= (const float*)d_in[4];
    const float* b1     = (const float*)d_in[5];
    const float* gm     = (const float*)d_in[6];
    const float* bm     = (const float*)d_in[7];
    const float* w2     = (const float*)d_in[8];
    const float* b2     = (const float*)d_in[9];
    const float* go     = (const float*)d_in[10];
    const float* bo     = (const float*)d_in[11];
    const float* lin_w  = (const float*)d_in[12];
    const float* lin_b  = (const float*)d_in[13];
    float* out = (float*)d_out;

    int N = in_sizes[0];
    int E = in_sizes[1] / 2;
    float invN = 1.f / (float)N;

    fused_all<<<PB, NT>>>(x, ei, batch, w1_0, w1_rest, b1, gm, bm,
                          w2, b2, go, bo, lin_w, lin_b, out,
                          N, E, in_sizes[2], invN);
}